// round 6
// baseline (speedup 1.0000x reference)
#include <cuda_runtime.h>
#include <cuda_bf16.h>
#include <math.h>
#include <type_traits>

// Problem constants (fixed shapes)
#define NND 100000
#define NED 1600000
#define NTOT (NED + NND)           // CSR capacity: valid edges + self loops
#define NGRAPH 64
#define SCAN_B ((NND + 255) / 256) // 391 scan blocks

// -------- device scratch --------
__device__ __align__(16) __nv_bfloat16 g_hb[NND * 64];    // bf16 GEMM output (gather source)
__device__ __align__(16) __nv_bfloat16 g_ho[NND * 64];    // bf16 aggregate output (next GEMM input)
__device__ float g_aS[NND];
__device__ float g_aD[NND];
__device__ int   g_rowoff[NND + 1];
__device__ int   g_cursor[NND];
__device__ int   g_scanmeta[1 + SCAN_B];                  // [0]=ticket, [1+b]=packed state
__device__ __align__(8) int2 g_colev[NTOT];               // paired {src, ev bits}

// packed f32x2 FMA (Blackwell FFMA2 — only reachable via PTX)
__device__ __forceinline__ unsigned long long ffma2(
    unsigned long long a, unsigned long long b, unsigned long long c) {
    unsigned long long d;
    asm("fma.rn.f32x2 %0, %1, %2, %3;" : "=l"(d) : "l"(a), "l"(b), "l"(c));
    return d;
}
__device__ __forceinline__ unsigned long long bcast2(float x) {
    unsigned long long r;
    asm("mov.b64 %0, {%1, %1};" : "=l"(r) : "r"(__float_as_uint(x)));
    return r;
}
__device__ __forceinline__ unsigned pack_bf16x2(float a, float b) {
    unsigned r;
    asm("cvt.rn.bf16x2.f32 %0, %1, %2;" : "=r"(r) : "f"(b), "f"(a));
    return r;
}

// ---------------------------------------------------------------------------
// CSR build (cursor + scanmeta pre-zeroed by memsetAsync)
// ---------------------------------------------------------------------------
__global__ void k_count(const int* __restrict__ ei, int E) {
    int e4 = blockIdx.x * blockDim.x + threadIdx.x;   // 4 edges per thread
    if (4 * e4 < E) {
        int4 s = reinterpret_cast<const int4*>(ei)[e4];
        int4 d = reinterpret_cast<const int4*>(ei + E)[e4];
        if (s.x != d.x) atomicAdd(&g_cursor[d.x], 1);
        if (s.y != d.y) atomicAdd(&g_cursor[d.y], 1);
        if (s.z != d.z) atomicAdd(&g_cursor[d.z], 1);
        if (s.w != d.w) atomicAdd(&g_cursor[d.w], 1);
    }
}

// Single-pass decoupled-lookback scan of (deg+1), + self-loop insert, + out init.
// State word: value<<2 | flag (1=partial, 2=prefix). Max value 1.7M << 2^29.
__global__ __launch_bounds__(256) void k_scan_lb(int n, float* out, const float* __restrict__ bf) {
    __shared__ int sh[256];
    __shared__ int sbid, sprev;
    int tid = threadIdx.x;
    if (tid == 0) sbid = atomicAdd(&g_scanmeta[0], 1);   // ticket = ordered chunk id
    __syncthreads();
    int bid = sbid;
    if (bid == 0 && tid < NGRAPH) out[tid] = bf[0];

    int i = bid * 256 + tid;
    int v = (i < n) ? (g_cursor[i] + 1) : 0;             // +1 = self loop
    sh[tid] = v;
    __syncthreads();
    #pragma unroll
    for (int off = 1; off < 256; off <<= 1) {
        int t = (tid >= off) ? sh[tid - off] : 0;
        __syncthreads();
        sh[tid] += t;
        __syncthreads();
    }
    int total = sh[255];

    if (tid == 0) {
        atomicExch(&g_scanmeta[1 + bid], (total << 2) | 1);   // publish partial
        int sum = 0;
        for (int j = bid - 1; j >= 0; j--) {
            int s;
            do { s = atomicAdd(&g_scanmeta[1 + j], 0); } while ((s & 3) == 0);
            sum += (s >> 2);
            if ((s & 3) == 2) break;                          // hit a full prefix
        }
        atomicExch(&g_scanmeta[1 + bid], ((sum + total) << 2) | 2);
        sprev = sum;
    }
    __syncthreads();
    int base = sprev;
    if (i < n) {
        int p = base + sh[tid] - v;      // exclusive offset
        g_rowoff[i] = p;
        g_colev[p] = make_int2(i, 0);    // self loop, ev = 0.0f
        g_cursor[i] = p + 1;
    }
    if (bid == SCAN_B - 1 && tid == 255) g_rowoff[n] = base + total;
}

__global__ void k_scatter(const int* __restrict__ ei, const float* __restrict__ ea, int E) {
    int e4 = blockIdx.x * blockDim.x + threadIdx.x;
    if (4 * e4 < E) {
        int4 s = reinterpret_cast<const int4*>(ei)[e4];
        int4 d = reinterpret_cast<const int4*>(ei + E)[e4];
        float4 a = reinterpret_cast<const float4*>(ea)[e4];
        if (s.x != d.x) { int p = atomicAdd(&g_cursor[d.x], 1); g_colev[p] = make_int2(s.x, __float_as_int(a.x)); }
        if (s.y != d.y) { int p = atomicAdd(&g_cursor[d.y], 1); g_colev[p] = make_int2(s.y, __float_as_int(a.y)); }
        if (s.z != d.z) { int p = atomicAdd(&g_cursor[d.z], 1); g_colev[p] = make_int2(s.z, __float_as_int(a.z)); }
        if (s.w != d.w) { int p = atomicAdd(&g_cursor[d.w], 1); g_colev[p] = make_int2(s.w, __float_as_int(a.w)); }
    }
}

// ---------------------------------------------------------------------------
// GEMM (H = X @ W, bf16 store) + attention scalars via packed f32x2 FMA.
// Templated input type: fp32 (layer 0, from x) or bf16 (layers 1-2, from g_ho).
// ---------------------------------------------------------------------------
template<typename TIN>
__global__ __launch_bounds__(256) void k_gemm_att(
    const TIN* __restrict__ X, const float* __restrict__ W,
    const float* __restrict__ att, int n)
{
    __shared__ __align__(16) float Ws[64 * 64];
    __shared__ float sAtt[130];
    int tid = threadIdx.x;
    #pragma unroll
    for (int i = tid; i < 1024; i += 256)
        reinterpret_cast<float4*>(Ws)[i] = reinterpret_cast<const float4*>(W)[i];
    if (tid < 129) sAtt[tid] = att[tid];
    __syncthreads();

    int row = blockIdx.x * 256 + tid;
    if (row >= n) return;

    unsigned long long acc[32];   // 64 fp32 accumulators packed as f32x2
    #pragma unroll
    for (int j = 0; j < 32; j++) acc[j] = 0ULL;

    #pragma unroll
    for (int h = 0; h < 2; h++) {
        float xs[32];
        if constexpr (std::is_same_v<TIN, float>) {
            const float4* Xr = reinterpret_cast<const float4*>(X + (size_t)row * 64);
            #pragma unroll
            for (int q = 0; q < 8; q++) {
                float4 t = Xr[h * 8 + q];
                xs[4 * q] = t.x; xs[4 * q + 1] = t.y; xs[4 * q + 2] = t.z; xs[4 * q + 3] = t.w;
            }
        } else {
            const uint4* Xr = reinterpret_cast<const uint4*>(X + (size_t)row * 64);
            #pragma unroll
            for (int q = 0; q < 4; q++) {
                uint4 t = Xr[h * 4 + q];
                unsigned wd[4] = {t.x, t.y, t.z, t.w};
                #pragma unroll
                for (int u = 0; u < 4; u++) {
                    float2 f = __bfloat1622float2(*reinterpret_cast<__nv_bfloat162*>(&wd[u]));
                    xs[8 * q + 2 * u] = f.x; xs[8 * q + 2 * u + 1] = f.y;
                }
            }
        }
        #pragma unroll
        for (int k = 0; k < 32; k++) {
            unsigned long long xx = bcast2(xs[k]);
            const ulonglong2* Wr = reinterpret_cast<const ulonglong2*>(Ws + (h * 32 + k) * 64);
            #pragma unroll
            for (int j = 0; j < 16; j++) {
                ulonglong2 w = Wr[j];
                acc[2 * j]     = ffma2(xx, w.x, acc[2 * j]);
                acc[2 * j + 1] = ffma2(xx, w.y, acc[2 * j + 1]);
            }
        }
    }

    float ad = 0.0f, as = 0.0f;
    #pragma unroll
    for (int j = 0; j < 32; j++) {
        float2 f = *reinterpret_cast<float2*>(&acc[j]);
        ad += f.x * sAtt[2 * j]      + f.y * sAtt[2 * j + 1];
        as += f.x * sAtt[64 + 2 * j] + f.y * sAtt[64 + 2 * j + 1];
    }
    g_aD[row] = ad;
    g_aS[row] = as;

    uint4* Hr = reinterpret_cast<uint4*>(g_hb + (size_t)row * 64);
    #pragma unroll
    for (int q = 0; q < 8; q++) {
        uint4 v;
        float2 f0 = *reinterpret_cast<float2*>(&acc[4 * q]);
        float2 f1 = *reinterpret_cast<float2*>(&acc[4 * q + 1]);
        float2 f2 = *reinterpret_cast<float2*>(&acc[4 * q + 2]);
        float2 f3 = *reinterpret_cast<float2*>(&acc[4 * q + 3]);
        v.x = pack_bf16x2(f0.x, f0.y);
        v.y = pack_bf16x2(f1.x, f1.y);
        v.z = pack_bf16x2(f2.x, f2.y);
        v.w = pack_bf16x2(f3.x, f3.y);
        Hr[q] = v;
    }
}

// ---------------------------------------------------------------------------
// Aggregation: warp per node, single pass (logits bounded -> exp safe).
// Lane covers features (2*lane, 2*lane+1) via one bf16x2 word per edge.
// Non-final: writes bf16x2 to OUT (g_ho). FINAL: fused pool + linear head.
// ---------------------------------------------------------------------------
template<bool FINAL>
__global__ __launch_bounds__(256) void k_aggregate(
    const float* __restrict__ att, const float* __restrict__ bias,
    unsigned* __restrict__ OUT,
    const int* __restrict__ batch, const float* __restrict__ Wf,
    float* __restrict__ out, int n)
{
    __shared__ float sh[NGRAPH];
    __shared__ float sWf[64];
    int tid = threadIdx.x;
    if (FINAL) {
        if (tid < NGRAPH) sh[tid] = 0.0f;
        if (tid < 64) sWf[tid] = Wf[tid];
        __syncthreads();
    }

    int gwarp = (blockIdx.x * blockDim.x + tid) >> 5;
    int lane = tid & 31;
    bool active = gwarp < n;

    float sx = 0.0f, sy = 0.0f, dl = 0.0f;

    if (active) {
        int start = g_rowoff[gwarp];
        int end   = g_rowoff[gwarp + 1];
        float attE = __ldg(&att[128]);
        float adn  = g_aD[gwarp];
        const unsigned* Hw = reinterpret_cast<const unsigned*>(g_hb);

        for (int base = start; base < end; base += 32) {
            int cn = min(32, end - base);
            int c = 0;
            float w = 0.0f;
            if (lane < cn) {
                int2 ce = __ldg(&g_colev[base + lane]);
                c = ce.x;
                float e = __int_as_float(ce.y);
                float l = adn + __ldg(&g_aS[c]) + e * attE;
                l = (l >= 0.0f) ? l : 0.2f * l;
                w = __expf(l);
            }
            dl += w;

            int j = 0;
            for (; j + 4 <= cn; j += 4) {
                int c0 = __shfl_sync(0xffffffffu, c, j);
                int c1 = __shfl_sync(0xffffffffu, c, j + 1);
                int c2 = __shfl_sync(0xffffffffu, c, j + 2);
                int c3 = __shfl_sync(0xffffffffu, c, j + 3);
                float w0 = __shfl_sync(0xffffffffu, w, j);
                float w1 = __shfl_sync(0xffffffffu, w, j + 1);
                float w2 = __shfl_sync(0xffffffffu, w, j + 2);
                float w3 = __shfl_sync(0xffffffffu, w, j + 3);
                unsigned v0 = __ldg(&Hw[(size_t)c0 * 32 + lane]);
                unsigned v1 = __ldg(&Hw[(size_t)c1 * 32 + lane]);
                unsigned v2 = __ldg(&Hw[(size_t)c2 * 32 + lane]);
                unsigned v3 = __ldg(&Hw[(size_t)c3 * 32 + lane]);
                float2 f0 = __bfloat1622float2(*reinterpret_cast<__nv_bfloat162*>(&v0));
                float2 f1 = __bfloat1622float2(*reinterpret_cast<__nv_bfloat162*>(&v1));
                float2 f2 = __bfloat1622float2(*reinterpret_cast<__nv_bfloat162*>(&v2));
                float2 f3 = __bfloat1622float2(*reinterpret_cast<__nv_bfloat162*>(&v3));
                sx += w0 * f0.x + w1 * f1.x + w2 * f2.x + w3 * f3.x;
                sy += w0 * f0.y + w1 * f1.y + w2 * f2.y + w3 * f3.y;
            }
            for (; j < cn; j++) {
                int cj   = __shfl_sync(0xffffffffu, c, j);
                float wj = __shfl_sync(0xffffffffu, w, j);
                unsigned v = __ldg(&Hw[(size_t)cj * 32 + lane]);
                float2 f = __bfloat1622float2(*reinterpret_cast<__nv_bfloat162*>(&v));
                sx += wj * f.x;
                sy += wj * f.y;
            }
        }
    }

    float dsum = dl;
    #pragma unroll
    for (int o = 16; o > 0; o >>= 1)
        dsum += __shfl_xor_sync(0xffffffffu, dsum, o);

    if (active) {
        float inv = 1.0f / dsum;
        float2 bv = __ldg(reinterpret_cast<const float2*>(bias) + lane);
        float rx = fmaxf(sx * inv + bv.x, 0.0f);
        float ry = fmaxf(sy * inv + bv.y, 0.0f);
        if (!FINAL) {
            OUT[(size_t)gwarp * 32 + lane] = pack_bf16x2(rx, ry);
        } else {
            float v = rx * sWf[2 * lane] + ry * sWf[2 * lane + 1];
            #pragma unroll
            for (int o = 16; o > 0; o >>= 1)
                v += __shfl_down_sync(0xffffffffu, v, o);
            if (lane == 0) atomicAdd(&sh[batch[gwarp]], v);
        }
    }
    if (FINAL) {
        __syncthreads();
        if (tid < NGRAPH && sh[tid] != 0.0f) atomicAdd(&out[tid], sh[tid]);
    }
}

// ---------------------------------------------------------------------------
extern "C" void kernel_launch(void* const* d_in, const int* in_sizes, int n_in,
                              void* d_out, int out_size)
{
    const float* x   = (const float*)d_in[0];
    const int*   ei  = (const int*)d_in[1];
    const float* ea  = (const float*)d_in[2];
    const int*   bat = (const int*)d_in[3];
    const float* W[3]   = {(const float*)d_in[4], (const float*)d_in[7], (const float*)d_in[10]};
    const float* att[3] = {(const float*)d_in[5], (const float*)d_in[8], (const float*)d_in[11]};
    const float* b[3]   = {(const float*)d_in[6], (const float*)d_in[9], (const float*)d_in[12]};
    const float* Wf = (const float*)d_in[13];
    const float* bf = (const float*)d_in[14];
    float* out = (float*)d_out;

    __nv_bfloat16* ho;
    cudaGetSymbolAddress((void**)&ho, g_ho);
    int* cur;
    cudaGetSymbolAddress((void**)&cur, g_cursor);
    int* meta;
    cudaGetSymbolAddress((void**)&meta, g_scanmeta);

    const int N = NND, E = NED;
    int nodeBlocks = (N + 255) / 256;          // 391
    int edge4Blocks = (E / 4 + 255) / 256;     // 1563
    int warpBlocks = (N + 7) / 8;              // 12500

    // --- CSR build ---
    cudaMemsetAsync(cur, 0, N * sizeof(int), 0);
    cudaMemsetAsync(meta, 0, (1 + SCAN_B) * sizeof(int), 0);
    k_count<<<edge4Blocks, 256>>>(ei, E);
    k_scan_lb<<<SCAN_B, 256>>>(N, out, bf);
    k_scatter<<<edge4Blocks, 256>>>(ei, ea, E);

    // --- layer 0 ---
    k_gemm_att<float><<<nodeBlocks, 256>>>(x, W[0], att[0], N);
    k_aggregate<false><<<warpBlocks, 256>>>(att[0], b[0], (unsigned*)ho, bat, Wf, out, N);
    // --- layer 1 ---
    k_gemm_att<__nv_bfloat16><<<nodeBlocks, 256>>>(ho, W[1], att[1], N);
    k_aggregate<false><<<warpBlocks, 256>>>(att[1], b[1], (unsigned*)ho, bat, Wf, out, N);
    // --- layer 2 (fused pool + head) ---
    k_gemm_att<__nv_bfloat16><<<nodeBlocks, 256>>>(ho, W[2], att[2], N);
    k_aggregate<true><<<warpBlocks, 256>>>(att[2], b[2], nullptr, bat, Wf, out, N);
}

// round 7
// speedup vs baseline: 1.0140x; 1.0140x over previous
#include <cuda_runtime.h>
#include <cuda_bf16.h>
#include <math.h>
#include <type_traits>

// Problem constants (fixed shapes)
#define NND 100000
#define NED 1600000
#define NTOT (NED + NND)           // CSR capacity: valid edges + self loops
#define NGRAPH 64
#define SCAN_B ((NND + 255) / 256) // 391 scan blocks

// -------- device scratch --------
__device__ __align__(16) __nv_bfloat16 g_hb[NND * 64];    // bf16 GEMM output (gather source)
__device__ __align__(16) __nv_bfloat16 g_ho[NND * 64];    // bf16 aggregate output (next GEMM input)
__device__ float g_aS[NND];
__device__ float g_aD[NND];
__device__ int   g_rowoff[NND + 1];
__device__ int   g_cursor[NND];
__device__ int   g_scanmeta[1 + SCAN_B];                  // [0]=ticket, [1+b]=packed state
__device__ __align__(8) int2 g_colev[NTOT];               // paired {src, ev bits}

// packed f32x2 FMA (Blackwell FFMA2 — only reachable via PTX)
__device__ __forceinline__ unsigned long long ffma2(
    unsigned long long a, unsigned long long b, unsigned long long c) {
    unsigned long long d;
    asm("fma.rn.f32x2 %0, %1, %2, %3;" : "=l"(d) : "l"(a), "l"(b), "l"(c));
    return d;
}
__device__ __forceinline__ unsigned long long bcast2(float x) {
    unsigned long long r;
    asm("mov.b64 %0, {%1, %1};" : "=l"(r) : "r"(__float_as_uint(x)));
    return r;
}
__device__ __forceinline__ unsigned pack_bf16x2(float a, float b) {
    unsigned r;
    asm("cvt.rn.bf16x2.f32 %0, %1, %2;" : "=r"(r) : "f"(b), "f"(a));
    return r;
}

// ---------------------------------------------------------------------------
// CSR build (cursor + scanmeta pre-zeroed by memsetAsync)
// ---------------------------------------------------------------------------
__global__ void k_count(const int* __restrict__ ei, int E) {
    int e4 = blockIdx.x * blockDim.x + threadIdx.x;   // 4 edges per thread
    if (4 * e4 < E) {
        int4 s = reinterpret_cast<const int4*>(ei)[e4];
        int4 d = reinterpret_cast<const int4*>(ei + E)[e4];
        if (s.x != d.x) atomicAdd(&g_cursor[d.x], 1);
        if (s.y != d.y) atomicAdd(&g_cursor[d.y], 1);
        if (s.z != d.z) atomicAdd(&g_cursor[d.z], 1);
        if (s.w != d.w) atomicAdd(&g_cursor[d.w], 1);
    }
}

// Single-pass decoupled-lookback scan of (deg+1), + self-loop insert, + out init.
__global__ __launch_bounds__(256) void k_scan_lb(int n, float* out, const float* __restrict__ bf) {
    __shared__ int sh[256];
    __shared__ int sbid, sprev;
    int tid = threadIdx.x;
    if (tid == 0) sbid = atomicAdd(&g_scanmeta[0], 1);   // ticket = ordered chunk id
    __syncthreads();
    int bid = sbid;
    if (bid == 0 && tid < NGRAPH) out[tid] = bf[0];

    int i = bid * 256 + tid;
    int v = (i < n) ? (g_cursor[i] + 1) : 0;             // +1 = self loop
    sh[tid] = v;
    __syncthreads();
    #pragma unroll
    for (int off = 1; off < 256; off <<= 1) {
        int t = (tid >= off) ? sh[tid - off] : 0;
        __syncthreads();
        sh[tid] += t;
        __syncthreads();
    }
    int total = sh[255];

    if (tid == 0) {
        atomicExch(&g_scanmeta[1 + bid], (total << 2) | 1);   // publish partial
        int sum = 0;
        for (int j = bid - 1; j >= 0; j--) {
            int s;
            do { s = atomicAdd(&g_scanmeta[1 + j], 0); } while ((s & 3) == 0);
            sum += (s >> 2);
            if ((s & 3) == 2) break;                          // hit a full prefix
        }
        atomicExch(&g_scanmeta[1 + bid], ((sum + total) << 2) | 2);
        sprev = sum;
    }
    __syncthreads();
    int base = sprev;
    if (i < n) {
        int p = base + sh[tid] - v;      // exclusive offset
        g_rowoff[i] = p;
        g_colev[p] = make_int2(i, 0);    // self loop, ev = 0.0f
        g_cursor[i] = p + 1;
    }
    if (bid == SCAN_B - 1 && tid == 255) g_rowoff[n] = base + total;
}

__global__ void k_scatter(const int* __restrict__ ei, const float* __restrict__ ea, int E) {
    int e4 = blockIdx.x * blockDim.x + threadIdx.x;
    if (4 * e4 < E) {
        int4 s = reinterpret_cast<const int4*>(ei)[e4];
        int4 d = reinterpret_cast<const int4*>(ei + E)[e4];
        float4 a = reinterpret_cast<const float4*>(ea)[e4];
        if (s.x != d.x) { int p = atomicAdd(&g_cursor[d.x], 1); g_colev[p] = make_int2(s.x, __float_as_int(a.x)); }
        if (s.y != d.y) { int p = atomicAdd(&g_cursor[d.y], 1); g_colev[p] = make_int2(s.y, __float_as_int(a.y)); }
        if (s.z != d.z) { int p = atomicAdd(&g_cursor[d.z], 1); g_colev[p] = make_int2(s.z, __float_as_int(a.z)); }
        if (s.w != d.w) { int p = atomicAdd(&g_cursor[d.w], 1); g_colev[p] = make_int2(s.w, __float_as_int(a.w)); }
    }
}

// ---------------------------------------------------------------------------
// GEMM (H = X @ W, bf16 store) + attention scalars via packed f32x2 FMA.
// TWO rows per thread (r, r+128) so each W LDS.128 feeds 4 FFMA2s — the
// round-6 profile showed the 1-row version saturating the smem crossbar
// (L1 71.8%) while FMA idled at 26%.
// ---------------------------------------------------------------------------
template<typename TIN>
__global__ __launch_bounds__(128) void k_gemm_att(
    const TIN* __restrict__ X, const float* __restrict__ W,
    const float* __restrict__ att, int n)
{
    __shared__ __align__(16) float Ws[64 * 64];
    __shared__ float sAtt[130];
    int tid = threadIdx.x;
    #pragma unroll
    for (int i = tid; i < 1024; i += 128)
        reinterpret_cast<float4*>(Ws)[i] = reinterpret_cast<const float4*>(W)[i];
    if (tid < 129) sAtt[tid] = att[tid];
    __syncthreads();

    int r0 = blockIdx.x * 256 + tid;
    int r1 = r0 + 128;
    if (r0 >= n) return;
    bool has1 = (r1 < n);

    unsigned long long acc0[32], acc1[32];   // 2 x 64 fp32 accumulators (f32x2)
    #pragma unroll
    for (int j = 0; j < 32; j++) { acc0[j] = 0ULL; acc1[j] = 0ULL; }

    #pragma unroll
    for (int h = 0; h < 4; h++) {            // 16 k-values per chunk
        float xs0[16], xs1[16];
        if constexpr (std::is_same_v<TIN, float>) {
            const float4* X0 = reinterpret_cast<const float4*>(X + (size_t)r0 * 64);
            const float4* X1 = reinterpret_cast<const float4*>(X + (size_t)(has1 ? r1 : r0) * 64);
            #pragma unroll
            for (int q = 0; q < 4; q++) {
                float4 t0 = X0[h * 4 + q];
                float4 t1 = X1[h * 4 + q];
                xs0[4*q] = t0.x; xs0[4*q+1] = t0.y; xs0[4*q+2] = t0.z; xs0[4*q+3] = t0.w;
                xs1[4*q] = t1.x; xs1[4*q+1] = t1.y; xs1[4*q+2] = t1.z; xs1[4*q+3] = t1.w;
            }
        } else {
            const uint4* X0 = reinterpret_cast<const uint4*>(X + (size_t)r0 * 64);
            const uint4* X1 = reinterpret_cast<const uint4*>(X + (size_t)(has1 ? r1 : r0) * 64);
            #pragma unroll
            for (int q = 0; q < 2; q++) {
                uint4 t0 = X0[h * 2 + q];
                uint4 t1 = X1[h * 2 + q];
                unsigned w0[4] = {t0.x, t0.y, t0.z, t0.w};
                unsigned w1[4] = {t1.x, t1.y, t1.z, t1.w};
                #pragma unroll
                for (int u = 0; u < 4; u++) {
                    float2 f0 = __bfloat1622float2(*reinterpret_cast<__nv_bfloat162*>(&w0[u]));
                    float2 f1 = __bfloat1622float2(*reinterpret_cast<__nv_bfloat162*>(&w1[u]));
                    xs0[8*q+2*u] = f0.x; xs0[8*q+2*u+1] = f0.y;
                    xs1[8*q+2*u] = f1.x; xs1[8*q+2*u+1] = f1.y;
                }
            }
        }
        #pragma unroll
        for (int k = 0; k < 16; k++) {
            unsigned long long xx0 = bcast2(xs0[k]);
            unsigned long long xx1 = bcast2(xs1[k]);
            const ulonglong2* Wr = reinterpret_cast<const ulonglong2*>(Ws + (h * 16 + k) * 64);
            #pragma unroll
            for (int j = 0; j < 16; j++) {
                ulonglong2 w = Wr[j];
                acc0[2*j]   = ffma2(xx0, w.x, acc0[2*j]);
                acc0[2*j+1] = ffma2(xx0, w.y, acc0[2*j+1]);
                acc1[2*j]   = ffma2(xx1, w.x, acc1[2*j]);
                acc1[2*j+1] = ffma2(xx1, w.y, acc1[2*j+1]);
            }
        }
    }

    // epilogue row 0
    {
        float ad = 0.0f, as = 0.0f;
        #pragma unroll
        for (int j = 0; j < 32; j++) {
            float2 f = *reinterpret_cast<float2*>(&acc0[j]);
            ad += f.x * sAtt[2*j]      + f.y * sAtt[2*j+1];
            as += f.x * sAtt[64+2*j]   + f.y * sAtt[64+2*j+1];
        }
        g_aD[r0] = ad;
        g_aS[r0] = as;
        uint4* Hr = reinterpret_cast<uint4*>(g_hb + (size_t)r0 * 64);
        #pragma unroll
        for (int q = 0; q < 8; q++) {
            uint4 v;
            float2 f0 = *reinterpret_cast<float2*>(&acc0[4*q]);
            float2 f1 = *reinterpret_cast<float2*>(&acc0[4*q+1]);
            float2 f2 = *reinterpret_cast<float2*>(&acc0[4*q+2]);
            float2 f3 = *reinterpret_cast<float2*>(&acc0[4*q+3]);
            v.x = pack_bf16x2(f0.x, f0.y);
            v.y = pack_bf16x2(f1.x, f1.y);
            v.z = pack_bf16x2(f2.x, f2.y);
            v.w = pack_bf16x2(f3.x, f3.y);
            Hr[q] = v;
        }
    }
    // epilogue row 1
    if (has1) {
        float ad = 0.0f, as = 0.0f;
        #pragma unroll
        for (int j = 0; j < 32; j++) {
            float2 f = *reinterpret_cast<float2*>(&acc1[j]);
            ad += f.x * sAtt[2*j]      + f.y * sAtt[2*j+1];
            as += f.x * sAtt[64+2*j]   + f.y * sAtt[64+2*j+1];
        }
        g_aD[r1] = ad;
        g_aS[r1] = as;
        uint4* Hr = reinterpret_cast<uint4*>(g_hb + (size_t)r1 * 64);
        #pragma unroll
        for (int q = 0; q < 8; q++) {
            uint4 v;
            float2 f0 = *reinterpret_cast<float2*>(&acc1[4*q]);
            float2 f1 = *reinterpret_cast<float2*>(&acc1[4*q+1]);
            float2 f2 = *reinterpret_cast<float2*>(&acc1[4*q+2]);
            float2 f3 = *reinterpret_cast<float2*>(&acc1[4*q+3]);
            v.x = pack_bf16x2(f0.x, f0.y);
            v.y = pack_bf16x2(f1.x, f1.y);
            v.z = pack_bf16x2(f2.x, f2.y);
            v.w = pack_bf16x2(f3.x, f3.y);
            Hr[q] = v;
        }
    }
}

// ---------------------------------------------------------------------------
// Aggregation: warp per node, single pass (logits bounded -> exp safe).
// Lane covers features (2*lane, 2*lane+1) via one bf16x2 word per edge.
// Non-final: writes bf16x2 to OUT (g_ho). FINAL: fused pool + linear head.
// ---------------------------------------------------------------------------
template<bool FINAL>
__global__ __launch_bounds__(256) void k_aggregate(
    const float* __restrict__ att, const float* __restrict__ bias,
    unsigned* __restrict__ OUT,
    const int* __restrict__ batch, const float* __restrict__ Wf,
    float* __restrict__ out, int n)
{
    __shared__ float sh[NGRAPH];
    __shared__ float sWf[64];
    int tid = threadIdx.x;
    if (FINAL) {
        if (tid < NGRAPH) sh[tid] = 0.0f;
        if (tid < 64) sWf[tid] = Wf[tid];
        __syncthreads();
    }

    int gwarp = (blockIdx.x * blockDim.x + tid) >> 5;
    int lane = tid & 31;
    bool active = gwarp < n;

    float sx = 0.0f, sy = 0.0f, dl = 0.0f;

    if (active) {
        int start = g_rowoff[gwarp];
        int end   = g_rowoff[gwarp + 1];
        float attE = __ldg(&att[128]);
        float adn  = g_aD[gwarp];
        const unsigned* Hw = reinterpret_cast<const unsigned*>(g_hb);

        for (int base = start; base < end; base += 32) {
            int cn = min(32, end - base);
            int c = 0;
            float w = 0.0f;
            if (lane < cn) {
                int2 ce = __ldg(&g_colev[base + lane]);
                c = ce.x;
                float e = __int_as_float(ce.y);
                float l = adn + __ldg(&g_aS[c]) + e * attE;
                l = (l >= 0.0f) ? l : 0.2f * l;
                w = __expf(l);
            }
            dl += w;

            int j = 0;
            for (; j + 4 <= cn; j += 4) {
                int c0 = __shfl_sync(0xffffffffu, c, j);
                int c1 = __shfl_sync(0xffffffffu, c, j + 1);
                int c2 = __shfl_sync(0xffffffffu, c, j + 2);
                int c3 = __shfl_sync(0xffffffffu, c, j + 3);
                float w0 = __shfl_sync(0xffffffffu, w, j);
                float w1 = __shfl_sync(0xffffffffu, w, j + 1);
                float w2 = __shfl_sync(0xffffffffu, w, j + 2);
                float w3 = __shfl_sync(0xffffffffu, w, j + 3);
                unsigned v0 = __ldg(&Hw[(size_t)c0 * 32 + lane]);
                unsigned v1 = __ldg(&Hw[(size_t)c1 * 32 + lane]);
                unsigned v2 = __ldg(&Hw[(size_t)c2 * 32 + lane]);
                unsigned v3 = __ldg(&Hw[(size_t)c3 * 32 + lane]);
                float2 f0 = __bfloat1622float2(*reinterpret_cast<__nv_bfloat162*>(&v0));
                float2 f1 = __bfloat1622float2(*reinterpret_cast<__nv_bfloat162*>(&v1));
                float2 f2 = __bfloat1622float2(*reinterpret_cast<__nv_bfloat162*>(&v2));
                float2 f3 = __bfloat1622float2(*reinterpret_cast<__nv_bfloat162*>(&v3));
                sx += w0 * f0.x + w1 * f1.x + w2 * f2.x + w3 * f3.x;
                sy += w0 * f0.y + w1 * f1.y + w2 * f2.y + w3 * f3.y;
            }
            for (; j < cn; j++) {
                int cj   = __shfl_sync(0xffffffffu, c, j);
                float wj = __shfl_sync(0xffffffffu, w, j);
                unsigned v = __ldg(&Hw[(size_t)cj * 32 + lane]);
                float2 f = __bfloat1622float2(*reinterpret_cast<__nv_bfloat162*>(&v));
                sx += wj * f.x;
                sy += wj * f.y;
            }
        }
    }

    float dsum = dl;
    #pragma unroll
    for (int o = 16; o > 0; o >>= 1)
        dsum += __shfl_xor_sync(0xffffffffu, dsum, o);

    if (active) {
        float inv = 1.0f / dsum;
        float2 bv = __ldg(reinterpret_cast<const float2*>(bias) + lane);
        float rx = fmaxf(sx * inv + bv.x, 0.0f);
        float ry = fmaxf(sy * inv + bv.y, 0.0f);
        if (!FINAL) {
            OUT[(size_t)gwarp * 32 + lane] = pack_bf16x2(rx, ry);
        } else {
            float v = rx * sWf[2 * lane] + ry * sWf[2 * lane + 1];
            #pragma unroll
            for (int o = 16; o > 0; o >>= 1)
                v += __shfl_down_sync(0xffffffffu, v, o);
            if (lane == 0) atomicAdd(&sh[batch[gwarp]], v);
        }
    }
    if (FINAL) {
        __syncthreads();
        if (tid < NGRAPH && sh[tid] != 0.0f) atomicAdd(&out[tid], sh[tid]);
    }
}

// ---------------------------------------------------------------------------
extern "C" void kernel_launch(void* const* d_in, const int* in_sizes, int n_in,
                              void* d_out, int out_size)
{
    const float* x   = (const float*)d_in[0];
    const int*   ei  = (const int*)d_in[1];
    const float* ea  = (const float*)d_in[2];
    const int*   bat = (const int*)d_in[3];
    const float* W[3]   = {(const float*)d_in[4], (const float*)d_in[7], (const float*)d_in[10]};
    const float* att[3] = {(const float*)d_in[5], (const float*)d_in[8], (const float*)d_in[11]};
    const float* b[3]   = {(const float*)d_in[6], (const float*)d_in[9], (const float*)d_in[12]};
    const float* Wf = (const float*)d_in[13];
    const float* bf = (const float*)d_in[14];
    float* out = (float*)d_out;

    __nv_bfloat16* ho;
    cudaGetSymbolAddress((void**)&ho, g_ho);
    int* cur;
    cudaGetSymbolAddress((void**)&cur, g_cursor);
    int* meta;
    cudaGetSymbolAddress((void**)&meta, g_scanmeta);

    const int N = NND, E = NED;
    int gemmBlocks = (N + 255) / 256;          // 391 (128 thr x 2 rows)
    int edge4Blocks = (E / 4 + 255) / 256;     // 1563
    int warpBlocks = (N + 7) / 8;              // 12500

    // --- CSR build ---
    cudaMemsetAsync(cur, 0, N * sizeof(int), 0);
    cudaMemsetAsync(meta, 0, (1 + SCAN_B) * sizeof(int), 0);
    k_count<<<edge4Blocks, 256>>>(ei, E);
    k_scan_lb<<<SCAN_B, 256>>>(N, out, bf);
    k_scatter<<<edge4Blocks, 256>>>(ei, ea, E);

    // --- layer 0 ---
    k_gemm_att<float><<<gemmBlocks, 128>>>(x, W[0], att[0], N);
    k_aggregate<false><<<warpBlocks, 256>>>(att[0], b[0], (unsigned*)ho, bat, Wf, out, N);
    // --- layer 1 ---
    k_gemm_att<__nv_bfloat16><<<gemmBlocks, 128>>>(ho, W[1], att[1], N);
    k_aggregate<false><<<warpBlocks, 256>>>(att[1], b[1], (unsigned*)ho, bat, Wf, out, N);
    // --- layer 2 (fused pool + head) ---
    k_gemm_att<__nv_bfloat16><<<gemmBlocks, 128>>>(ho, W[2], att[2], N);
    k_aggregate<true><<<warpBlocks, 256>>>(att[2], b[2], nullptr, bat, Wf, out, N);
}

// round 10
// speedup vs baseline: 1.0672x; 1.0525x over previous
#include <cuda_runtime.h>
#include <cuda_bf16.h>
#include <math.h>
#include <stdint.h>

// Problem constants (fixed shapes)
#define NND 100000
#define NED 1600000
#define NTOT (NED + NND)           // CSR capacity: valid edges + self loops
#define NGRAPH 64
#define SCAN_B ((NND + 255) / 256) // 391 scan blocks

// -------- device scratch --------
__device__ __align__(16) __nv_bfloat16 g_xb[NND * 64];      // bf16 copy of x
__device__ __align__(16) __nv_bfloat16 g_hb[NND * 64];      // bf16 GEMM output (gather source)
__device__ __align__(16) __nv_bfloat16 g_ho[NND * 64];      // bf16 aggregate output
__device__ __align__(16) __nv_bfloat16 g_wt[3][2][64 * 64]; // W^T bf16 {hi, lo residual}
__device__ float g_aS[NND];
__device__ float g_aD[NND];
__device__ int   g_rowoff[NND + 1];
__device__ int   g_cursor[NND];
__device__ int   g_scanmeta[1 + SCAN_B];
__device__ __align__(8) int2 g_colev[NTOT];

__device__ __forceinline__ unsigned pack_bf16x2(float a, float b) {
    unsigned r;
    asm("cvt.rn.bf16x2.f32 %0, %1, %2;" : "=r"(r) : "f"(b), "f"(a));
    return r;
}

// warp-level bf16 tensor-core MMA (valid at compute_103 — NOT tcgen05)
__device__ __forceinline__ void mma16816(float* c, uint32_t a0, uint32_t a1,
                                         uint32_t a2, uint32_t a3,
                                         uint32_t b0, uint32_t b1) {
    asm volatile(
        "mma.sync.aligned.m16n8k16.row.col.f32.bf16.bf16.f32 "
        "{%0,%1,%2,%3}, {%4,%5,%6,%7}, {%8,%9}, {%0,%1,%2,%3};"
        : "+f"(c[0]), "+f"(c[1]), "+f"(c[2]), "+f"(c[3])
        : "r"(a0), "r"(a1), "r"(a2), "r"(a3), "r"(b0), "r"(b1));
}

// ---------------------------------------------------------------------------
// Prep: x -> bf16; W -> W^T split into bf16 hi + bf16 lo residual
// ---------------------------------------------------------------------------
__global__ void k_prepx(const float* __restrict__ x) {
    int i = blockIdx.x * blockDim.x + threadIdx.x;
    if (4 * i < NND * 64) {
        float4 v = reinterpret_cast<const float4*>(x)[i];
        uint2 o;
        o.x = pack_bf16x2(v.x, v.y);
        o.y = pack_bf16x2(v.z, v.w);
        reinterpret_cast<uint2*>(g_xb)[i] = o;
    }
}
__global__ void k_prepw(const float* __restrict__ W0, const float* __restrict__ W1,
                        const float* __restrict__ W2) {
    const float* W = (blockIdx.x == 0) ? W0 : (blockIdx.x == 1) ? W1 : W2;
    __nv_bfloat16* hi = g_wt[blockIdx.x][0];
    __nv_bfloat16* lo = g_wt[blockIdx.x][1];
    for (int e = threadIdx.x; e < 64 * 64; e += blockDim.x) {
        int nn = e >> 6, kk = e & 63;
        float w = W[kk * 64 + nn];
        __nv_bfloat16 h = __float2bfloat16(w);
        hi[nn * 64 + kk] = h;
        lo[nn * 64 + kk] = __float2bfloat16(w - __bfloat162float(h));
    }
}

// ---------------------------------------------------------------------------
// CSR build (cursor + scanmeta pre-zeroed by memsetAsync)
// ---------------------------------------------------------------------------
__global__ void k_count(const int* __restrict__ ei, int E) {
    int e4 = blockIdx.x * blockDim.x + threadIdx.x;
    if (4 * e4 < E) {
        int4 s = reinterpret_cast<const int4*>(ei)[e4];
        int4 d = reinterpret_cast<const int4*>(ei + E)[e4];
        if (s.x != d.x) atomicAdd(&g_cursor[d.x], 1);
        if (s.y != d.y) atomicAdd(&g_cursor[d.y], 1);
        if (s.z != d.z) atomicAdd(&g_cursor[d.z], 1);
        if (s.w != d.w) atomicAdd(&g_cursor[d.w], 1);
    }
}

__global__ __launch_bounds__(256) void k_scan_lb(int n, float* out, const float* __restrict__ bf) {
    __shared__ int sh[256];
    __shared__ int sbid, sprev;
    int tid = threadIdx.x;
    if (tid == 0) sbid = atomicAdd(&g_scanmeta[0], 1);
    __syncthreads();
    int bid = sbid;
    if (bid == 0 && tid < NGRAPH) out[tid] = bf[0];

    int i = bid * 256 + tid;
    int v = (i < n) ? (g_cursor[i] + 1) : 0;
    sh[tid] = v;
    __syncthreads();
    #pragma unroll
    for (int off = 1; off < 256; off <<= 1) {
        int t = (tid >= off) ? sh[tid - off] : 0;
        __syncthreads();
        sh[tid] += t;
        __syncthreads();
    }
    int total = sh[255];

    if (tid == 0) {
        atomicExch(&g_scanmeta[1 + bid], (total << 2) | 1);
        int sum = 0;
        for (int j = bid - 1; j >= 0; j--) {
            int s;
            do { s = atomicAdd(&g_scanmeta[1 + j], 0); } while ((s & 3) == 0);
            sum += (s >> 2);
            if ((s & 3) == 2) break;
        }
        atomicExch(&g_scanmeta[1 + bid], ((sum + total) << 2) | 2);
        sprev = sum;
    }
    __syncthreads();
    int base = sprev;
    if (i < n) {
        int p = base + sh[tid] - v;
        g_rowoff[i] = p;
        g_colev[p] = make_int2(i, 0);
        g_cursor[i] = p + 1;
    }
    if (bid == SCAN_B - 1 && tid == 255) g_rowoff[n] = base + total;
}

__global__ void k_scatter(const int* __restrict__ ei, const float* __restrict__ ea, int E) {
    int e4 = blockIdx.x * blockDim.x + threadIdx.x;
    if (4 * e4 < E) {
        int4 s = reinterpret_cast<const int4*>(ei)[e4];
        int4 d = reinterpret_cast<const int4*>(ei + E)[e4];
        float4 a = reinterpret_cast<const float4*>(ea)[e4];
        if (s.x != d.x) { int p = atomicAdd(&g_cursor[d.x], 1); g_colev[p] = make_int2(s.x, __float_as_int(a.x)); }
        if (s.y != d.y) { int p = atomicAdd(&g_cursor[d.y], 1); g_colev[p] = make_int2(s.y, __float_as_int(a.y)); }
        if (s.z != d.z) { int p = atomicAdd(&g_cursor[d.z], 1); g_colev[p] = make_int2(s.z, __float_as_int(a.z)); }
        if (s.w != d.w) { int p = atomicAdd(&g_cursor[d.w], 1); g_colev[p] = make_int2(s.w, __float_as_int(a.w)); }
    }
}

// ---------------------------------------------------------------------------
// Tensor-core GEMM via mma.sync m16n8k16 bf16 with SPLIT-W (hi + lo):
// H = A@W_hi + A@W_lo kills the systematic W-rounding bias that failed
// round 9 (5.2e-3). 8 warps x 16 rows = 128 rows/CTA; B tiles in padded
// smem (33 words/row, conflict-free); A straight from global (L1-resident).
// ---------------------------------------------------------------------------
__global__ __launch_bounds__(256) void k_gemm_mma(
    const __nv_bfloat16* __restrict__ X, const __nv_bfloat16* __restrict__ Wt,
    const float* __restrict__ att, int n)
{
    __shared__ float sAtt[130];
    __shared__ uint32_t sWh[64 * 33];  // W_hi row n: 32 k-words + pad
    __shared__ uint32_t sWl[64 * 33];  // W_lo
    int tid = threadIdx.x;
    const uint32_t* Wt32 = reinterpret_cast<const uint32_t*>(Wt);
    #pragma unroll
    for (int i = tid; i < 2048; i += 256) {
        sWh[(i >> 5) * 33 + (i & 31)] = Wt32[i];
        sWl[(i >> 5) * 33 + (i & 31)] = Wt32[2048 + i];
    }
    if (tid < 129) sAtt[tid] = att[tid];
    __syncthreads();

    int warp = tid >> 5, lane = tid & 31;
    int gid = lane >> 2, tig = lane & 3;
    int r0 = blockIdx.x * 128 + warp * 16 + gid;
    int r1 = r0 + 8;
    int r0c = min(r0, n - 1), r1c = min(r1, n - 1);
    const uint32_t* Xw = reinterpret_cast<const uint32_t*>(X);

    float c[8][4];
    #pragma unroll
    for (int nt = 0; nt < 8; nt++)
        #pragma unroll
        for (int q = 0; q < 4; q++) c[nt][q] = 0.0f;

    #pragma unroll
    for (int kt = 0; kt < 4; kt++) {
        uint32_t a0 = Xw[(size_t)r0c * 32 + kt * 8 + tig];
        uint32_t a1 = Xw[(size_t)r1c * 32 + kt * 8 + tig];
        uint32_t a2 = Xw[(size_t)r0c * 32 + kt * 8 + tig + 4];
        uint32_t a3 = Xw[(size_t)r1c * 32 + kt * 8 + tig + 4];
        #pragma unroll
        for (int nt = 0; nt < 8; nt++) {
            int bi = (nt * 8 + gid) * 33 + kt * 8 + tig;
            mma16816(c[nt], a0, a1, a2, a3, sWh[bi], sWh[bi + 4]);
            mma16816(c[nt], a0, a1, a2, a3, sWl[bi], sWl[bi + 4]);
        }
    }

    // attention scalars: thread covers cols {nt*8 + tig*2, +1} of rows r0, r1
    float ad0 = 0.0f, as0 = 0.0f, ad1 = 0.0f, as1 = 0.0f;
    #pragma unroll
    for (int nt = 0; nt < 8; nt++) {
        float w0 = sAtt[nt * 8 + tig * 2],      w1 = sAtt[nt * 8 + tig * 2 + 1];
        float v0 = sAtt[64 + nt * 8 + tig * 2], v1 = sAtt[64 + nt * 8 + tig * 2 + 1];
        ad0 += c[nt][0] * w0 + c[nt][1] * w1;
        as0 += c[nt][0] * v0 + c[nt][1] * v1;
        ad1 += c[nt][2] * w0 + c[nt][3] * w1;
        as1 += c[nt][2] * v0 + c[nt][3] * v1;
    }
    #pragma unroll
    for (int o = 1; o <= 2; o <<= 1) {
        ad0 += __shfl_xor_sync(0xffffffffu, ad0, o);
        as0 += __shfl_xor_sync(0xffffffffu, as0, o);
        ad1 += __shfl_xor_sync(0xffffffffu, ad1, o);
        as1 += __shfl_xor_sync(0xffffffffu, as1, o);
    }
    if (tig == 0 && r0 < n) { g_aD[r0] = ad0; g_aS[r0] = as0; }
    if (tig == 0 && r1 < n) { g_aD[r1] = ad1; g_aS[r1] = as1; }

    uint32_t* H32 = reinterpret_cast<uint32_t*>(g_hb);
    if (r0 < n) {
        #pragma unroll
        for (int nt = 0; nt < 8; nt++)
            H32[(size_t)r0 * 32 + nt * 4 + tig] = pack_bf16x2(c[nt][0], c[nt][1]);
    }
    if (r1 < n) {
        #pragma unroll
        for (int nt = 0; nt < 8; nt++)
            H32[(size_t)r1 * 32 + nt * 4 + tig] = pack_bf16x2(c[nt][2], c[nt][3]);
    }
}

// ---------------------------------------------------------------------------
// Aggregation: warp per node, single pass (logits bounded -> exp safe).
// ---------------------------------------------------------------------------
template<bool FINAL>
__global__ __launch_bounds__(256) void k_aggregate(
    const float* __restrict__ att, const float* __restrict__ bias,
    unsigned* __restrict__ OUT,
    const int* __restrict__ batch, const float* __restrict__ Wf,
    float* __restrict__ out, int n)
{
    __shared__ float sh[NGRAPH];
    __shared__ float sWf[64];
    int tid = threadIdx.x;
    if (FINAL) {
        if (tid < NGRAPH) sh[tid] = 0.0f;
        if (tid < 64) sWf[tid] = Wf[tid];
        __syncthreads();
    }

    int gwarp = (blockIdx.x * blockDim.x + tid) >> 5;
    int lane = tid & 31;
    bool active = gwarp < n;

    float sx = 0.0f, sy = 0.0f, dl = 0.0f;

    if (active) {
        int start = g_rowoff[gwarp];
        int end   = g_rowoff[gwarp + 1];
        float attE = __ldg(&att[128]);
        float adn  = g_aD[gwarp];
        const unsigned* Hw = reinterpret_cast<const unsigned*>(g_hb);

        for (int base = start; base < end; base += 32) {
            int cn = min(32, end - base);
            int c = 0;
            float w = 0.0f;
            if (lane < cn) {
                int2 ce = __ldg(&g_colev[base + lane]);
                c = ce.x;
                float e = __int_as_float(ce.y);
                float l = adn + __ldg(&g_aS[c]) + e * attE;
                l = (l >= 0.0f) ? l : 0.2f * l;
                w = __expf(l);
            }
            dl += w;

            int j = 0;
            for (; j + 4 <= cn; j += 4) {
                int c0 = __shfl_sync(0xffffffffu, c, j);
                int c1 = __shfl_sync(0xffffffffu, c, j + 1);
                int c2 = __shfl_sync(0xffffffffu, c, j + 2);
                int c3 = __shfl_sync(0xffffffffu, c, j + 3);
                float w0 = __shfl_sync(0xffffffffu, w, j);
                float w1 = __shfl_sync(0xffffffffu, w, j + 1);
                float w2 = __shfl_sync(0xffffffffu, w, j + 2);
                float w3 = __shfl_sync(0xffffffffu, w, j + 3);
                unsigned v0 = __ldg(&Hw[(size_t)c0 * 32 + lane]);
                unsigned v1 = __ldg(&Hw[(size_t)c1 * 32 + lane]);
                unsigned v2 = __ldg(&Hw[(size_t)c2 * 32 + lane]);
                unsigned v3 = __ldg(&Hw[(size_t)c3 * 32 + lane]);
                float2 f0 = __bfloat1622float2(*reinterpret_cast<__nv_bfloat162*>(&v0));
                float2 f1 = __bfloat1622float2(*reinterpret_cast<__nv_bfloat162*>(&v1));
                float2 f2 = __bfloat1622float2(*reinterpret_cast<__nv_bfloat162*>(&v2));
                float2 f3 = __bfloat1622float2(*reinterpret_cast<__nv_bfloat162*>(&v3));
                sx += w0 * f0.x + w1 * f1.x + w2 * f2.x + w3 * f3.x;
                sy += w0 * f0.y + w1 * f1.y + w2 * f2.y + w3 * f3.y;
            }
            for (; j < cn; j++) {
                int cj   = __shfl_sync(0xffffffffu, c, j);
                float wj = __shfl_sync(0xffffffffu, w, j);
                unsigned v = __ldg(&Hw[(size_t)cj * 32 + lane]);
                float2 f = __bfloat1622float2(*reinterpret_cast<__nv_bfloat162*>(&v));
                sx += wj * f.x;
                sy += wj * f.y;
            }
        }
    }

    float dsum = dl;
    #pragma unroll
    for (int o = 16; o > 0; o >>= 1)
        dsum += __shfl_xor_sync(0xffffffffu, dsum, o);

    if (active) {
        float inv = 1.0f / dsum;
        float2 bv = __ldg(reinterpret_cast<const float2*>(bias) + lane);
        float rx = fmaxf(sx * inv + bv.x, 0.0f);
        float ry = fmaxf(sy * inv + bv.y, 0.0f);
        if (!FINAL) {
            OUT[(size_t)gwarp * 32 + lane] = pack_bf16x2(rx, ry);
        } else {
            float v = rx * sWf[2 * lane] + ry * sWf[2 * lane + 1];
            #pragma unroll
            for (int o = 16; o > 0; o >>= 1)
                v += __shfl_down_sync(0xffffffffu, v, o);
            if (lane == 0) atomicAdd(&sh[batch[gwarp]], v);
        }
    }
    if (FINAL) {
        __syncthreads();
        if (tid < NGRAPH && sh[tid] != 0.0f) atomicAdd(&out[tid], sh[tid]);
    }
}

// ---------------------------------------------------------------------------
extern "C" void kernel_launch(void* const* d_in, const int* in_sizes, int n_in,
                              void* d_out, int out_size)
{
    const float* x   = (const float*)d_in[0];
    const int*   ei  = (const int*)d_in[1];
    const float* ea  = (const float*)d_in[2];
    const int*   bat = (const int*)d_in[3];
    const float* W[3]   = {(const float*)d_in[4], (const float*)d_in[7], (const float*)d_in[10]};
    const float* att[3] = {(const float*)d_in[5], (const float*)d_in[8], (const float*)d_in[11]};
    const float* b[3]   = {(const float*)d_in[6], (const float*)d_in[9], (const float*)d_in[12]};
    const float* Wf = (const float*)d_in[13];
    const float* bf = (const float*)d_in[14];
    float* out = (float*)d_out;

    __nv_bfloat16 *xb, *ho, *wt;
    cudaGetSymbolAddress((void**)&xb, g_xb);
    cudaGetSymbolAddress((void**)&ho, g_ho);
    cudaGetSymbolAddress((void**)&wt, g_wt);
    int* cur;
    cudaGetSymbolAddress((void**)&cur, g_cursor);
    int* meta;
    cudaGetSymbolAddress((void**)&meta, g_scanmeta);

    const int N = NND, E = NED;
    int mmaBlocks   = (N + 127) / 128;         // 782
    int edge4Blocks = (E / 4 + 255) / 256;     // 1563
    int warpBlocks  = (N + 7) / 8;             // 12500
    int prepxBlocks = (N * 64 / 4 + 255) / 256;

    // --- prep + CSR build ---
    cudaMemsetAsync(cur, 0, N * sizeof(int), 0);
    cudaMemsetAsync(meta, 0, (1 + SCAN_B) * sizeof(int), 0);
    k_prepx<<<prepxBlocks, 256>>>(x);
    k_prepw<<<3, 256>>>(W[0], W[1], W[2]);
    k_count<<<edge4Blocks, 256>>>(ei, E);
    k_scan_lb<<<SCAN_B, 256>>>(N, out, bf);
    k_scatter<<<edge4Blocks, 256>>>(ei, ea, E);

    // --- layer 0 ---
    k_gemm_mma<<<mmaBlocks, 256>>>(xb, wt, att[0], N);
    k_aggregate<false><<<warpBlocks, 256>>>(att[0], b[0], (unsigned*)ho, bat, Wf, out, N);
    // --- layer 1 ---
    k_gemm_mma<<<mmaBlocks, 256>>>(ho, wt + 2 * 64 * 64, att[1], N);
    k_aggregate<false><<<warpBlocks, 256>>>(att[1], b[1], (unsigned*)ho, bat, Wf, out, N);
    // --- layer 2 (fused pool + head) ---
    k_gemm_mma<<<mmaBlocks, 256>>>(ho, wt + 4 * 64 * 64, att[2], N);
    k_aggregate<true><<<warpBlocks, 256>>>(att[2], b[2], nullptr, bat, Wf, out, N);
}

// round 11
// speedup vs baseline: 1.1437x; 1.0717x over previous
#include <cuda_runtime.h>
#include <cuda_bf16.h>
#include <math.h>
#include <stdint.h>

// Problem constants (fixed shapes)
#define NND 100000
#define NED 1600000
#define NTOT (NED + NND)           // CSR capacity: valid edges + self loops
#define NGRAPH 64
#define SCAN_B ((NND + 255) / 256) // 391 scan blocks
#define E4_B ((NED / 4 + 255) / 256)      // 1563 count/scatter blocks
#define PX_B ((NND * 16 + 255) / 256)     // 6250 prepx blocks
#define MMA_B ((NND + 127) / 128)         // 782 gemm blocks
#define GEMM_SMEM 17440

// -------- device scratch --------
__device__ __align__(16) __nv_bfloat16 g_xb[NND * 64];      // bf16 copy of x
__device__ __align__(16) __nv_bfloat16 g_hb[NND * 64];      // bf16 GEMM output (gather source)
__device__ __align__(16) __nv_bfloat16 g_ho[NND * 64];      // bf16 aggregate output
__device__ __align__(16) __nv_bfloat16 g_wt[3][2][64 * 64]; // W^T bf16 {hi, lo residual}
__device__ float g_aS[NND];
__device__ float g_aD[NND];
__device__ int   g_rowoff[NND + 1];
__device__ int   g_cursor[NND];
__device__ int   g_scanmeta[1 + SCAN_B];
__device__ __align__(8) int2 g_colev[NTOT];

__device__ __forceinline__ unsigned pack_bf16x2(float a, float b) {
    unsigned r;
    asm("cvt.rn.bf16x2.f32 %0, %1, %2;" : "=r"(r) : "f"(b), "f"(a));
    return r;
}

// warp-level bf16 tensor-core MMA (valid at compute_103 — NOT tcgen05)
__device__ __forceinline__ void mma16816(float* c, uint32_t a0, uint32_t a1,
                                         uint32_t a2, uint32_t a3,
                                         uint32_t b0, uint32_t b1) {
    asm volatile(
        "mma.sync.aligned.m16n8k16.row.col.f32.bf16.bf16.f32 "
        "{%0,%1,%2,%3}, {%4,%5,%6,%7}, {%8,%9}, {%0,%1,%2,%3};"
        : "+f"(c[0]), "+f"(c[1]), "+f"(c[2]), "+f"(c[3])
        : "r"(a0), "r"(a1), "r"(a2), "r"(a3), "r"(b0), "r"(b1));
}

// ---------------------------------------------------------------------------
// GEMM body (callable from fused + standalone kernels). Split-W bf16 MMA:
// H = A@W_hi + A@W_lo. 8 warps x 16 rows = 128 rows per block `blk`.
// ---------------------------------------------------------------------------
__device__ __forceinline__ void gemm_body(char* sm,
    const __nv_bfloat16* __restrict__ X, const __nv_bfloat16* __restrict__ Wt,
    const float* __restrict__ att, int n, int blk)
{
    float* sAtt = reinterpret_cast<float*>(sm);
    uint32_t* sWh = reinterpret_cast<uint32_t*>(sm + 544);
    uint32_t* sWl = sWh + 64 * 33;
    int tid = threadIdx.x;
    const uint32_t* Wt32 = reinterpret_cast<const uint32_t*>(Wt);
    #pragma unroll
    for (int i = tid; i < 2048; i += 256) {
        sWh[(i >> 5) * 33 + (i & 31)] = Wt32[i];
        sWl[(i >> 5) * 33 + (i & 31)] = Wt32[2048 + i];
    }
    if (tid < 129) sAtt[tid] = att[tid];
    __syncthreads();

    int warp = tid >> 5, lane = tid & 31;
    int gid = lane >> 2, tig = lane & 3;
    int r0 = blk * 128 + warp * 16 + gid;
    int r1 = r0 + 8;
    int r0c = min(r0, n - 1), r1c = min(r1, n - 1);
    const uint32_t* Xw = reinterpret_cast<const uint32_t*>(X);

    float c[8][4];
    #pragma unroll
    for (int nt = 0; nt < 8; nt++)
        #pragma unroll
        for (int q = 0; q < 4; q++) c[nt][q] = 0.0f;

    #pragma unroll
    for (int kt = 0; kt < 4; kt++) {
        uint32_t a0 = Xw[(size_t)r0c * 32 + kt * 8 + tig];
        uint32_t a1 = Xw[(size_t)r1c * 32 + kt * 8 + tig];
        uint32_t a2 = Xw[(size_t)r0c * 32 + kt * 8 + tig + 4];
        uint32_t a3 = Xw[(size_t)r1c * 32 + kt * 8 + tig + 4];
        #pragma unroll
        for (int nt = 0; nt < 8; nt++) {
            int bi = (nt * 8 + gid) * 33 + kt * 8 + tig;
            mma16816(c[nt], a0, a1, a2, a3, sWh[bi], sWh[bi + 4]);
            mma16816(c[nt], a0, a1, a2, a3, sWl[bi], sWl[bi + 4]);
        }
    }

    float ad0 = 0.0f, as0 = 0.0f, ad1 = 0.0f, as1 = 0.0f;
    #pragma unroll
    for (int nt = 0; nt < 8; nt++) {
        float w0 = sAtt[nt * 8 + tig * 2],      w1 = sAtt[nt * 8 + tig * 2 + 1];
        float v0 = sAtt[64 + nt * 8 + tig * 2], v1 = sAtt[64 + nt * 8 + tig * 2 + 1];
        ad0 += c[nt][0] * w0 + c[nt][1] * w1;
        as0 += c[nt][0] * v0 + c[nt][1] * v1;
        ad1 += c[nt][2] * w0 + c[nt][3] * w1;
        as1 += c[nt][2] * v0 + c[nt][3] * v1;
    }
    #pragma unroll
    for (int o = 1; o <= 2; o <<= 1) {
        ad0 += __shfl_xor_sync(0xffffffffu, ad0, o);
        as0 += __shfl_xor_sync(0xffffffffu, as0, o);
        ad1 += __shfl_xor_sync(0xffffffffu, ad1, o);
        as1 += __shfl_xor_sync(0xffffffffu, as1, o);
    }
    if (tig == 0 && r0 < n) { g_aD[r0] = ad0; g_aS[r0] = as0; }
    if (tig == 0 && r1 < n) { g_aD[r1] = ad1; g_aS[r1] = as1; }

    uint32_t* H32 = reinterpret_cast<uint32_t*>(g_hb);
    if (r0 < n) {
        #pragma unroll
        for (int nt = 0; nt < 8; nt++)
            H32[(size_t)r0 * 32 + nt * 4 + tig] = pack_bf16x2(c[nt][0], c[nt][1]);
    }
    if (r1 < n) {
        #pragma unroll
        for (int nt = 0; nt < 8; nt++)
            H32[(size_t)r1 * 32 + nt * 4 + tig] = pack_bf16x2(c[nt][2], c[nt][3]);
    }
}

// ---------------------------------------------------------------------------
// Scan body: decoupled lookback with WARP-PARALLEL window (32 preds/step) —
// the round-10 profile showed the serial thread-0 lookback costing 15.8us.
// ---------------------------------------------------------------------------
__device__ __forceinline__ void scan_body(char* sm, int n, float* out,
                                          const float* __restrict__ bf)
{
    int* sh = reinterpret_cast<int*>(sm);
    volatile int* sbid  = sh + 256;
    volatile int* sprev = sh + 257;
    int tid = threadIdx.x;
    if (tid == 0) *sbid = atomicAdd(&g_scanmeta[0], 1);
    __syncthreads();
    int bid = *sbid;
    if (bid == 0 && tid < NGRAPH) out[tid] = bf[0];

    int i = bid * 256 + tid;
    int v = (i < n) ? (g_cursor[i] + 1) : 0;   // +1 = self loop
    sh[tid] = v;
    __syncthreads();
    #pragma unroll
    for (int off = 1; off < 256; off <<= 1) {
        int t = (tid >= off) ? sh[tid - off] : 0;
        __syncthreads();
        sh[tid] += t;
        __syncthreads();
    }
    int total = sh[255];

    if (bid == 0) {
        if (tid == 0) { atomicExch(&g_scanmeta[1], (total << 2) | 2); *sprev = 0; }
    } else {
        if (tid == 0) atomicExch(&g_scanmeta[1 + bid], (total << 2) | 1);
        if (tid < 32) {
            int sum = 0;
            int j = bid - 1 - tid;
            while (true) {
                int s = 0;
                if (j >= 0) {
                    do { s = atomicAdd(&g_scanmeta[1 + j], 0); } while (!(s & 3));
                }
                unsigned pm = __ballot_sync(0xffffffffu, (j >= 0) && ((s & 3) == 2));
                int lim = pm ? (__ffs(pm) - 1) : 32;
                int val = (j >= 0 && tid <= lim) ? (s >> 2) : 0;
                #pragma unroll
                for (int o = 16; o > 0; o >>= 1)
                    val += __shfl_xor_sync(0xffffffffu, val, o);
                sum += val;
                if (pm) break;          // found a full prefix; block 0 guarantees one
                j -= 32;
            }
            if (tid == 0) {
                atomicExch(&g_scanmeta[1 + bid], ((sum + total) << 2) | 2);
                *sprev = sum;
            }
        }
    }
    __syncthreads();
    int base = *sprev;
    if (i < n) {
        int p = base + sh[tid] - v;      // exclusive offset
        g_rowoff[i] = p;
        g_colev[p] = make_int2(i, 0);    // self loop, ev = 0.0f
        g_cursor[i] = p + 1;
    }
    if (bid == SCAN_B - 1 && tid == 255) g_rowoff[n] = base + total;
}

// ---------------------------------------------------------------------------
// Role bodies for edge passes / prep
// ---------------------------------------------------------------------------
__device__ __forceinline__ void count_body(const int* __restrict__ ei, int E, int blk) {
    int e4 = blk * 256 + threadIdx.x;
    if (4 * e4 < E) {
        int4 s = reinterpret_cast<const int4*>(ei)[e4];
        int4 d = reinterpret_cast<const int4*>(ei + E)[e4];
        if (s.x != d.x) atomicAdd(&g_cursor[d.x], 1);
        if (s.y != d.y) atomicAdd(&g_cursor[d.y], 1);
        if (s.z != d.z) atomicAdd(&g_cursor[d.z], 1);
        if (s.w != d.w) atomicAdd(&g_cursor[d.w], 1);
    }
}
__device__ __forceinline__ void scatter_body(const int* __restrict__ ei,
                                             const float* __restrict__ ea, int E, int blk) {
    int e4 = blk * 256 + threadIdx.x;
    if (4 * e4 < E) {
        int4 s = reinterpret_cast<const int4*>(ei)[e4];
        int4 d = reinterpret_cast<const int4*>(ei + E)[e4];
        float4 a = reinterpret_cast<const float4*>(ea)[e4];
        if (s.x != d.x) { int p = atomicAdd(&g_cursor[d.x], 1); g_colev[p] = make_int2(s.x, __float_as_int(a.x)); }
        if (s.y != d.y) { int p = atomicAdd(&g_cursor[d.y], 1); g_colev[p] = make_int2(s.y, __float_as_int(a.y)); }
        if (s.z != d.z) { int p = atomicAdd(&g_cursor[d.z], 1); g_colev[p] = make_int2(s.z, __float_as_int(a.z)); }
        if (s.w != d.w) { int p = atomicAdd(&g_cursor[d.w], 1); g_colev[p] = make_int2(s.w, __float_as_int(a.w)); }
    }
}
__device__ __forceinline__ void prepx_body(const float* __restrict__ x, int blk) {
    int i = blk * 256 + threadIdx.x;
    if (4 * i < NND * 64) {
        float4 v = reinterpret_cast<const float4*>(x)[i];
        uint2 o;
        o.x = pack_bf16x2(v.x, v.y);
        o.y = pack_bf16x2(v.z, v.w);
        reinterpret_cast<uint2*>(g_xb)[i] = o;
    }
}
__device__ __forceinline__ void prepw_body(const float* __restrict__ W, int layer) {
    __nv_bfloat16* hi = g_wt[layer][0];
    __nv_bfloat16* lo = g_wt[layer][1];
    for (int e = threadIdx.x; e < 64 * 64; e += 256) {
        int nn = e >> 6, kk = e & 63;
        float w = W[kk * 64 + nn];
        __nv_bfloat16 h = __float2bfloat16(w);
        hi[nn * 64 + kk] = h;
        lo[nn * 64 + kk] = __float2bfloat16(w - __bfloat162float(h));
    }
}

// ---------------------------------------------------------------------------
// Fused launches (block-role split = overlap without streams)
// ---------------------------------------------------------------------------
// K1: count ∪ prepw ∪ prepx (all independent; prep hides under count)
__global__ __launch_bounds__(256) void k_prep_count(
    const float* __restrict__ x, const float* __restrict__ W0,
    const float* __restrict__ W1, const float* __restrict__ W2,
    const int* __restrict__ ei, int E)
{
    int b = blockIdx.x;
    if (b < E4_B) count_body(ei, E, b);
    else if (b < E4_B + 3) prepw_body(b == E4_B ? W0 : (b == E4_B + 1 ? W1 : W2), b - E4_B);
    else prepx_body(x, b - E4_B - 3);
}

// K2: scan (warp-lookback, standalone)
__global__ __launch_bounds__(256) void k_scan_lb(int n, float* out, const float* __restrict__ bf) {
    __shared__ __align__(16) char sm[1040];
    scan_body(sm, n, out, bf);
}

// K3: scatter ∪ gemm0 (independent; gemm0 hides under scatter)
__global__ __launch_bounds__(256) void k_scatter_gemm(
    const int* __restrict__ ei, const float* __restrict__ ea, int E,
    const __nv_bfloat16* __restrict__ X, const __nv_bfloat16* __restrict__ Wt,
    const float* __restrict__ att, int n)
{
    __shared__ __align__(16) char sm[GEMM_SMEM];
    int b = blockIdx.x;
    if (b < E4_B) scatter_body(ei, ea, E, b);
    else gemm_body(sm, X, Wt, att, n, b - E4_B);
}

// Standalone GEMM for layers 1-2
__global__ __launch_bounds__(256) void k_gemm_mma(
    const __nv_bfloat16* __restrict__ X, const __nv_bfloat16* __restrict__ Wt,
    const float* __restrict__ att, int n)
{
    __shared__ __align__(16) char sm[GEMM_SMEM];
    gemm_body(sm, X, Wt, att, n, blockIdx.x);
}

// ---------------------------------------------------------------------------
// Aggregation: warp per node, single pass (logits bounded -> exp safe).
// ---------------------------------------------------------------------------
template<bool FINAL>
__global__ __launch_bounds__(256) void k_aggregate(
    const float* __restrict__ att, const float* __restrict__ bias,
    unsigned* __restrict__ OUT,
    const int* __restrict__ batch, const float* __restrict__ Wf,
    float* __restrict__ out, int n)
{
    __shared__ float sh[NGRAPH];
    __shared__ float sWf[64];
    int tid = threadIdx.x;
    if (FINAL) {
        if (tid < NGRAPH) sh[tid] = 0.0f;
        if (tid < 64) sWf[tid] = Wf[tid];
        __syncthreads();
    }

    int gwarp = (blockIdx.x * blockDim.x + tid) >> 5;
    int lane = tid & 31;
    bool active = gwarp < n;

    float sx = 0.0f, sy = 0.0f, dl = 0.0f;

    if (active) {
        int start = g_rowoff[gwarp];
        int end   = g_rowoff[gwarp + 1];
        float attE = __ldg(&att[128]);
        float adn  = g_aD[gwarp];
        const unsigned* Hw = reinterpret_cast<const unsigned*>(g_hb);

        for (int base = start; base < end; base += 32) {
            int cn = min(32, end - base);
            int c = 0;
            float w = 0.0f;
            if (lane < cn) {
                int2 ce = __ldg(&g_colev[base + lane]);
                c = ce.x;
                float e = __int_as_float(ce.y);
                float l = adn + __ldg(&g_aS[c]) + e * attE;
                l = (l >= 0.0f) ? l : 0.2f * l;
                w = __expf(l);
            }
            dl += w;

            int j = 0;
            for (; j + 4 <= cn; j += 4) {
                int c0 = __shfl_sync(0xffffffffu, c, j);
                int c1 = __shfl_sync(0xffffffffu, c, j + 1);
                int c2 = __shfl_sync(0xffffffffu, c, j + 2);
                int c3 = __shfl_sync(0xffffffffu, c, j + 3);
                float w0 = __shfl_sync(0xffffffffu, w, j);
                float w1 = __shfl_sync(0xffffffffu, w, j + 1);
                float w2 = __shfl_sync(0xffffffffu, w, j + 2);
                float w3 = __shfl_sync(0xffffffffu, w, j + 3);
                unsigned v0 = __ldg(&Hw[(size_t)c0 * 32 + lane]);
                unsigned v1 = __ldg(&Hw[(size_t)c1 * 32 + lane]);
                unsigned v2 = __ldg(&Hw[(size_t)c2 * 32 + lane]);
                unsigned v3 = __ldg(&Hw[(size_t)c3 * 32 + lane]);
                float2 f0 = __bfloat1622float2(*reinterpret_cast<__nv_bfloat162*>(&v0));
                float2 f1 = __bfloat1622float2(*reinterpret_cast<__nv_bfloat162*>(&v1));
                float2 f2 = __bfloat1622float2(*reinterpret_cast<__nv_bfloat162*>(&v2));
                float2 f3 = __bfloat1622float2(*reinterpret_cast<__nv_bfloat162*>(&v3));
                sx += w0 * f0.x + w1 * f1.x + w2 * f2.x + w3 * f3.x;
                sy += w0 * f0.y + w1 * f1.y + w2 * f2.y + w3 * f3.y;
            }
            for (; j < cn; j++) {
                int cj   = __shfl_sync(0xffffffffu, c, j);
                float wj = __shfl_sync(0xffffffffu, w, j);
                unsigned v = __ldg(&Hw[(size_t)cj * 32 + lane]);
                float2 f = __bfloat1622float2(*reinterpret_cast<__nv_bfloat162*>(&v));
                sx += wj * f.x;
                sy += wj * f.y;
            }
        }
    }

    float dsum = dl;
    #pragma unroll
    for (int o = 16; o > 0; o >>= 1)
        dsum += __shfl_xor_sync(0xffffffffu, dsum, o);

    if (active) {
        float inv = 1.0f / dsum;
        float2 bv = __ldg(reinterpret_cast<const float2*>(bias) + lane);
        float rx = fmaxf(sx * inv + bv.x, 0.0f);
        float ry = fmaxf(sy * inv + bv.y, 0.0f);
        if (!FINAL) {
            OUT[(size_t)gwarp * 32 + lane] = pack_bf16x2(rx, ry);
        } else {
            float v = rx * sWf[2 * lane] + ry * sWf[2 * lane + 1];
            #pragma unroll
            for (int o = 16; o > 0; o >>= 1)
                v += __shfl_down_sync(0xffffffffu, v, o);
            if (lane == 0) atomicAdd(&sh[batch[gwarp]], v);
        }
    }
    if (FINAL) {
        __syncthreads();
        if (tid < NGRAPH && sh[tid] != 0.0f) atomicAdd(&out[tid], sh[tid]);
    }
}

// ---------------------------------------------------------------------------
extern "C" void kernel_launch(void* const* d_in, const int* in_sizes, int n_in,
                              void* d_out, int out_size)
{
    const float* x   = (const float*)d_in[0];
    const int*   ei  = (const int*)d_in[1];
    const float* ea  = (const float*)d_in[2];
    const int*   bat = (const int*)d_in[3];
    const float* W[3]   = {(const float*)d_in[4], (const float*)d_in[7], (const float*)d_in[10]};
    const float* att[3] = {(const float*)d_in[5], (const float*)d_in[8], (const float*)d_in[11]};
    const float* b[3]   = {(const float*)d_in[6], (const float*)d_in[9], (const float*)d_in[12]};
    const float* Wf = (const float*)d_in[13];
    const float* bf = (const float*)d_in[14];
    float* out = (float*)d_out;

    __nv_bfloat16 *xb, *ho, *wt;
    cudaGetSymbolAddress((void**)&xb, g_xb);
    cudaGetSymbolAddress((void**)&ho, g_ho);
    cudaGetSymbolAddress((void**)&wt, g_wt);
    int* cur;
    cudaGetSymbolAddress((void**)&cur, g_cursor);
    int* meta;
    cudaGetSymbolAddress((void**)&meta, g_scanmeta);

    const int N = NND, E = NED;
    int warpBlocks = (N + 7) / 8;              // 12500

    // --- prep + CSR build (fused for overlap) ---
    cudaMemsetAsync(cur, 0, N * sizeof(int), 0);
    cudaMemsetAsync(meta, 0, (1 + SCAN_B) * sizeof(int), 0);
    k_prep_count<<<E4_B + 3 + PX_B, 256>>>(x, W[0], W[1], W[2], ei, E);
    k_scan_lb<<<SCAN_B, 256>>>(N, out, bf);
    k_scatter_gemm<<<E4_B + MMA_B, 256>>>(ei, ea, E, xb, wt, att[0], N);

    // --- layer 0 aggregate ---
    k_aggregate<false><<<warpBlocks, 256>>>(att[0], b[0], (unsigned*)ho, bat, Wf, out, N);
    // --- layer 1 ---
    k_gemm_mma<<<MMA_B, 256>>>(ho, wt + 2 * 64 * 64, att[1], N);
    k_aggregate<false><<<warpBlocks, 256>>>(att[1], b[1], (unsigned*)ho, bat, Wf, out, N);
    // --- layer 2 (fused pool + head) ---
    k_gemm_mma<<<MMA_B, 256>>>(ho, wt + 4 * 64 * 64, att[2], N);
    k_aggregate<true><<<warpBlocks, 256>>>(att[2], b[2], nullptr, bat, Wf, out, N);
}